// round 13
// baseline (speedup 1.0000x reference)
#include <cuda_runtime.h>
#include <cuda_bf16.h>
#include <math.h>
#include <stdint.h>

#define B_   8
#define S_   1024
#define D_   1152
#define H_   16
#define HD_  72
#define M_   (B_*S_)          // 8192
#define N3_  (3*D_)           // 3456
#define BHSHD (B_*H_*S_*HD_)  // 9437184
#define SCL 0.170044411294f   // 72^-0.5 * log2(e)

// Scratch (device globals; no allocations allowed)
__device__ float g_qkv[3u*BHSHD];                         // fp32 [3][B][H][S][HD]
__device__ __nv_bfloat16 g_qkvh[3u*BHSHD], g_qkvl[3u*BHSHD];
__device__ __nv_bfloat16 g_attnh[(size_t)M_*D_], g_attnl[(size_t)M_*D_];
__device__ __nv_bfloat16 g_hidh[(size_t)M_*D_],  g_hidl[(size_t)M_*D_];
__device__ __nv_bfloat16 g_wqh[(size_t)N3_*D_],  g_wql[(size_t)N3_*D_];
__device__ __nv_bfloat16 g_wph[(size_t)D_*D_],   g_wpl[(size_t)D_*D_];

// ---------------------------------------------------------------------------
// helpers
// ---------------------------------------------------------------------------
__device__ __forceinline__ uint32_t pk(__nv_bfloat16 a, __nv_bfloat16 b) {
    return (uint32_t)__bfloat16_as_ushort(a) | ((uint32_t)__bfloat16_as_ushort(b) << 16);
}
__device__ __forceinline__ void cvt_hi_lo(float4 v, uint2& hi, uint2& lo) {
    __nv_bfloat16 hx = __float2bfloat16(v.x), hy = __float2bfloat16(v.y);
    __nv_bfloat16 hz = __float2bfloat16(v.z), hw = __float2bfloat16(v.w);
    __nv_bfloat16 lx = __float2bfloat16(v.x - __bfloat162float(hx));
    __nv_bfloat16 ly = __float2bfloat16(v.y - __bfloat162float(hy));
    __nv_bfloat16 lz = __float2bfloat16(v.z - __bfloat162float(hz));
    __nv_bfloat16 lw = __float2bfloat16(v.w - __bfloat162float(hw));
    hi.x = pk(hx, hy); hi.y = pk(hz, hw);
    lo.x = pk(lx, ly); lo.y = pk(lz, lw);
}
__device__ __forceinline__ void mma16816(float* c, const uint32_t* a, const uint32_t* b) {
    asm volatile(
        "mma.sync.aligned.m16n8k16.row.col.f32.bf16.bf16.f32 "
        "{%0,%1,%2,%3}, {%4,%5,%6,%7}, {%8,%9}, {%0,%1,%2,%3};"
        : "+f"(c[0]), "+f"(c[1]), "+f"(c[2]), "+f"(c[3])
        : "r"(a[0]), "r"(a[1]), "r"(a[2]), "r"(a[3]), "r"(b[0]), "r"(b[1]));
}
__device__ __forceinline__ void ldm4(uint32_t* r, uint32_t a) {
    asm volatile("ldmatrix.sync.aligned.m8n8.x4.shared.b16 {%0,%1,%2,%3}, [%4];"
        : "=r"(r[0]), "=r"(r[1]), "=r"(r[2]), "=r"(r[3]) : "r"(a));
}
__device__ __forceinline__ void ldm4t(uint32_t* r, uint32_t a) {
    asm volatile("ldmatrix.sync.aligned.m8n8.x4.trans.shared.b16 {%0,%1,%2,%3}, [%4];"
        : "=r"(r[0]), "=r"(r[1]), "=r"(r[2]), "=r"(r[3]) : "r"(a));
}
__device__ __forceinline__ void ldm2t(uint32_t* r, uint32_t a) {
    asm volatile("ldmatrix.sync.aligned.m8n8.x2.trans.shared.b16 {%0,%1}, [%2];"
        : "=r"(r[0]), "=r"(r[1]) : "r"(a));
}
__device__ __forceinline__ void cp16(uint32_t dst, const void* src) {
    asm volatile("cp.async.cg.shared.global [%0], [%1], 16;" :: "r"(dst), "l"(src));
}
#define CP_COMMIT() asm volatile("cp.async.commit_group;")
template <int N> __device__ __forceinline__ void cp_wait() {
    asm volatile("cp.async.wait_group %0;" :: "n"(N));
}
// FMA-pipe 2^x for x <= 0 (no MUFU)
__device__ __forceinline__ float exp2p(float d) {
    d = fmaxf(d, -100.f);
    const float MAGIC = 12582912.f;
    float frnd = d + MAGIC;
    int   i    = __float_as_int(frnd) - __float_as_int(MAGIC);
    float f    = d - (frnd - MAGIC);
    float y = 9.6181e-3f;
    y = fmaf(y, f, 5.54906e-2f);
    y = fmaf(y, f, 2.402265e-1f);
    y = fmaf(y, f, 6.931472e-1f);
    y = fmaf(y, f, 1.f);
    return __int_as_float(__float_as_int(y) + (i << 23));
}

// ---------------------------------------------------------------------------
// fp32 -> hi/lo bf16 converters
// ---------------------------------------------------------------------------
template <int WHICH>
__global__ void cvt_pair(const float* __restrict__ src, int n4)
{
    int i = blockIdx.x * blockDim.x + threadIdx.x;
    if (i >= n4) return;
    __nv_bfloat16* h = (WHICH == 0) ? g_hidh : (WHICH == 1) ? g_wqh : g_wph;
    __nv_bfloat16* l = (WHICH == 0) ? g_hidl : (WHICH == 1) ? g_wql : g_wpl;
    float4 v = ((const float4*)src)[i];
    uint2 hi, lo; cvt_hi_lo(v, hi, lo);
    ((uint2*)h)[i] = hi;
    ((uint2*)l)[i] = lo;
}

// ---------------------------------------------------------------------------
// bf16 HMMA GEMM (unchanged from R12 best): BM=256, BN=128, BK=32, 512 thr.
// ---------------------------------------------------------------------------
#define GSTG 61440
#define GSMEM (2*GSTG)     // 122880

template <int MODE>
__global__ __launch_bounds__(512)
void gemm_bf16(const float* __restrict__ bias, float* __restrict__ C, int N)
{
    extern __shared__ __nv_bfloat16 dsm[];
    const uint32_t sb = (uint32_t)__cvta_generic_to_shared(dsm);
    const int tid = threadIdx.x, wid = tid >> 5, lane = tid & 31;
    const int bm0 = blockIdx.y * 256, bn0 = blockIdx.x * 128;
    const int wm = (wid >> 2) * 64, wn = (wid & 3) * 32;
    const int K = D_;

    const __nv_bfloat16* Ah_ = MODE ? g_hidh : g_attnh;
    const __nv_bfloat16* Al_ = MODE ? g_hidl : g_attnl;
    const __nv_bfloat16* Bh_ = MODE ? g_wqh  : g_wph;
    const __nv_bfloat16* Bl_ = MODE ? g_wql  : g_wpl;

    float acc[4][4][4];
#pragma unroll
    for (int mt = 0; mt < 4; mt++)
#pragma unroll
        for (int nt = 0; nt < 4; nt++)
#pragma unroll
            for (int r = 0; r < 4; r++) acc[mt][nt][r] = 0.f;

    const int rowL = tid >> 2;
    const int kof  = (tid & 3) * 8;

    auto issue = [&](int c, int s) {
        const uint32_t stb = sb + s * GSTG;
        const int k0 = c * 32;
        cp16(stb +         rowL * 80 + kof * 2,         Ah_ + (size_t)(bm0 + rowL) * K + k0 + kof);
        cp16(stb +         (rowL + 128) * 80 + kof * 2, Ah_ + (size_t)(bm0 + rowL + 128) * K + k0 + kof);
        cp16(stb + 20480 + rowL * 80 + kof * 2,         Al_ + (size_t)(bm0 + rowL) * K + k0 + kof);
        cp16(stb + 20480 + (rowL + 128) * 80 + kof * 2, Al_ + (size_t)(bm0 + rowL + 128) * K + k0 + kof);
        cp16(stb + 40960 + rowL * 80 + kof * 2,         Bh_ + (size_t)(bn0 + rowL) * K + k0 + kof);
        cp16(stb + 51200 + rowL * 80 + kof * 2,         Bl_ + (size_t)(bn0 + rowL) * K + k0 + kof);
        CP_COMMIT();
    };

    const int NCH = K / 32;
    issue(0, 0);
    for (int c = 0; c < NCH; c++) {
        const int s = c & 1;
        if (c + 1 < NCH) { issue(c + 1, s ^ 1); cp_wait<1>(); }
        else             { cp_wait<0>(); }
        __syncthreads();
        const uint32_t stb = sb + s * GSTG;
        const uint32_t abase = stb + ((wm + (lane & 15)) * 40 + ((lane >> 4) * 8)) * 2;
        const uint32_t bbase = stb + 40960 +
            ((wn + ((lane >> 4) * 8) + (lane & 7)) * 40 + (((lane >> 3) & 1) * 8)) * 2;
#pragma unroll
        for (int ks = 0; ks < 2; ks++) {
            uint32_t bhf[8], blf[8];
            ldm4(&bhf[0], bbase + ks * 32);
            ldm4(&bhf[4], bbase + ks * 32 + 1280);
            ldm4(&blf[0], bbase + ks * 32 + 10240);
            ldm4(&blf[4], bbase + ks * 32 + 10240 + 1280);
#pragma unroll
            for (int mt = 0; mt < 4; mt++) {
                uint32_t ah[4], al[4];
                ldm4(ah, abase + ks * 32 + mt * 1280);
                ldm4(al, abase + ks * 32 + mt * 1280 + 20480);
#pragma unroll
                for (int nt = 0; nt < 4; nt++) {
                    mma16816(acc[mt][nt], ah, &bhf[nt * 2]);
                    mma16816(acc[mt][nt], ah, &blf[nt * 2]);
                    mma16816(acc[mt][nt], al, &bhf[nt * 2]);
                }
            }
        }
        __syncthreads();
    }

    const int g = lane >> 2, tg = (lane & 3) * 2;
#pragma unroll
    for (int mt = 0; mt < 4; mt++) {
#pragma unroll
        for (int nt = 0; nt < 4; nt++) {
#pragma unroll
            for (int r = 0; r < 4; r++) {
                const int m = bm0 + wm + mt * 16 + g + (r >= 2 ? 8 : 0);
                const int n = bn0 + wn + nt * 8 + tg + (r & 1);
                const float v = acc[mt][nt][r] + bias[n];
                if (MODE == 0) {
                    C[(size_t)m * N + n] = v;
                } else {
                    const int b = m >> 10, s2 = m & 1023;
                    const int t = n / D_;
                    const int rr = n - t * D_;
                    const int h = rr / HD_;
                    const int hd = rr - h * HD_;
                    g_qkv[(((size_t)(t * B_ + b) * H_ + h) * S_ + s2) * HD_ + hd] = v;
                }
            }
        }
    }
}

// ---------------------------------------------------------------------------
// RoPE + convert (unchanged)
// ---------------------------------------------------------------------------
__global__ void rope_cvt(const float* __restrict__ cosp,
                         const float* __restrict__ sinp)
{
    const int total = 3 * B_ * H_ * S_ * 36;
    int idx = blockIdx.x * blockDim.x + threadIdx.x;
    if (idx >= total) return;
    const int i = idx % 36;
    const int row = idx / 36;
    const int s = row & (S_ - 1);
    const int t = row >> 17;
    const float* base = g_qkv + (size_t)row * HD_;
    float x1 = base[i], x2 = base[i + 36];
    float y1, y2;
    if (t < 2) {
        y1 = x1 * cosp[s * HD_ + i]      - x2 * sinp[s * HD_ + i];
        y2 = x2 * cosp[s * HD_ + i + 36] + x1 * sinp[s * HD_ + i + 36];
        if (t == 0) { y1 *= SCL; y2 *= SCL; }
    } else { y1 = x1; y2 = x2; }
    __nv_bfloat16 h1 = __float2bfloat16(y1);
    __nv_bfloat16 h2 = __float2bfloat16(y2);
    const size_t o1 = (size_t)row * HD_ + i, o2 = o1 + 36;
    g_qkvh[o1] = h1; g_qkvl[o1] = __float2bfloat16(y1 - __bfloat162float(h1));
    g_qkvh[o2] = h2; g_qkvl[o2] = __float2bfloat16(y2 - __bfloat162float(h2));
}

// ---------------------------------------------------------------------------
// HMMA flash attention v4: 32 q-rows per warp (2 m16 subtiles) so every K/V
// fragment load feeds 2x the MMAs. Q persistent in smem; Q frags reloaded
// per chunk (keeps regs ~190). CTA = 256 thr, q-tile 256, grid y = 4.
// smem (bytes): Qh@0 (256x88), Ql@45056, Kh@90112, Kl@101376,
//               Vh@112640, Vl@123904; total 135168.
// ---------------------------------------------------------------------------
#define AQL 45056
#define AKH 90112
#define AKL 101376
#define AVH 112640
#define AVL 123904
#define ASM_TOT 135168

__global__ __launch_bounds__(256)
void attn3()
{
    extern __shared__ __nv_bfloat16 sm[];
    const uint32_t sb = (uint32_t)__cvta_generic_to_shared(sm);
    const int tid = threadIdx.x, w = tid >> 5, lane = tid & 31;
    const int g = lane >> 2, tg = (lane & 3) * 2;
    const int bh = blockIdx.x, q0 = blockIdx.y * 256;
    const int b = bh >> 4, h = bh & 15;

    const __nv_bfloat16* qh = g_qkvh;
    const __nv_bfloat16* ql = g_qkvl;
    const __nv_bfloat16* kh = g_qkvh + (size_t)BHSHD;
    const __nv_bfloat16* kl = g_qkvl + (size_t)BHSHD;
    const __nv_bfloat16* vh = g_qkvh + (size_t)2 * BHSHD;
    const __nv_bfloat16* vl = g_qkvl + (size_t)2 * BHSHD;

    // ---- stage Q (persistent; already SCL-scaled) ----
    for (int i = tid; i < 256 * 18; i += 256) {
        const int row = i / 18, c4 = (i % 18) * 4;
        const size_t go = ((size_t)(bh << 10) + q0 + row) * HD_ + c4;
        *(uint2*)&sm[row * 88 + c4]         = *(const uint2*)&qh[go];
        *(uint2*)&sm[22528 + row * 88 + c4] = *(const uint2*)&ql[go];
    }
    for (int i = tid; i < 2048; i += 256) {     // zero Q pad cols 72..79 (hi+lo)
        const int arr = i >> 10, rem = i & 1023;
        const int row = rem >> 2, c = (rem & 3) * 2;
        *(uint32_t*)&sm[arr * 22528 + row * 88 + 72 + c] = 0u;
    }
    // ---- zero K pad cols 72..79 (hi+lo), staged region written below ----
    for (int i = tid; i < 512; i += 256) {
        const int arr = i >> 8, rem = i & 255;
        const int row = rem >> 2, c = (rem & 3) * 2;
        *(uint32_t*)&sm[45056 + arr * 5632 + row * 88 + 72 + c] = 0u;
    }
    __syncthreads();

    float oA[9][4], oB[9][4];
#pragma unroll
    for (int n = 0; n < 9; n++)
#pragma unroll
        for (int r = 0; r < 4; r++) { oA[n][r] = 0.f; oB[n][r] = 0.f; }
    float mA0 = -1e30f, mA1 = -1e30f, lA0 = 0.f, lA1 = 0.f;
    float mB0 = -1e30f, mB1 = -1e30f, lB0 = 0.f, lB1 = 0.f;

    const uint32_t qbA = sb + ((w * 32 + (lane & 15)) * 88 + ((lane >> 4) * 8)) * 2;
    const uint32_t qbB = qbA + 2816;   // +16 rows
    const uint32_t kb0 = sb + AKH +
        ((((lane >> 4) * 8) + (lane & 7)) * 88 + (((lane >> 3) & 1) * 8)) * 2;

    for (int j0 = 0; j0 < S_; j0 += 64) {
        // ---- stage K and V (straight row copies, bf16) ----
        for (int i = tid; i < 64 * 18; i += 256) {
            const int row = i / 18, c4 = (i % 18) * 4;
            const size_t go = ((size_t)(bh << 10) + j0 + row) * HD_ + c4;
            *(uint2*)&sm[45056 + row * 88 + c4] = *(const uint2*)&kh[go];
            *(uint2*)&sm[50688 + row * 88 + c4] = *(const uint2*)&kl[go];
            *(uint2*)&sm[56320 + row * 88 + c4] = *(const uint2*)&vh[go];
            *(uint2*)&sm[61952 + row * 88 + c4] = *(const uint2*)&vl[go];
        }
        __syncthreads();

        // ---- S = Q.K^T for both subtiles ----
        float sA[8][4], sB[8][4];
#pragma unroll
        for (int n = 0; n < 8; n++)
#pragma unroll
            for (int r = 0; r < 4; r++) { sA[n][r] = 0.f; sB[n][r] = 0.f; }
#pragma unroll
        for (int c = 0; c < 5; c++) {
            uint32_t qah[4], qal[4], qbh[4], qbl[4];
            ldm4(qah, qbA + c * 32);
            ldm4(qal, qbA + c * 32 + AQL);
            ldm4(qbh, qbB + c * 32);
            ldm4(qbl, qbB + c * 32 + AQL);
#pragma unroll
            for (int ktp = 0; ktp < 4; ktp++) {
                uint32_t fh[4], fl[4];
                ldm4(fh, kb0 + c * 32 + ktp * 2816);
                ldm4(fl, kb0 + c * 32 + ktp * 2816 + 11264);
                mma16816(sA[ktp * 2],     qah, &fh[0]);
                mma16816(sA[ktp * 2],     qah, &fl[0]);
                mma16816(sA[ktp * 2],     qal, &fh[0]);
                mma16816(sA[ktp * 2 + 1], qah, &fh[2]);
                mma16816(sA[ktp * 2 + 1], qah, &fl[2]);
                mma16816(sA[ktp * 2 + 1], qal, &fh[2]);
                mma16816(sB[ktp * 2],     qbh, &fh[0]);
                mma16816(sB[ktp * 2],     qbh, &fl[0]);
                mma16816(sB[ktp * 2],     qbl, &fh[0]);
                mma16816(sB[ktp * 2 + 1], qbh, &fh[2]);
                mma16816(sB[ktp * 2 + 1], qbh, &fl[2]);
                mma16816(sB[ktp * 2 + 1], qbl, &fh[2]);
            }
        }

        // ---- online softmax, subtile A ----
        {
            float mx0 = sA[0][0], mx1 = sA[0][2];
#pragma unroll
            for (int n = 0; n < 8; n++) {
                mx0 = fmaxf(mx0, fmaxf(sA[n][0], sA[n][1]));
                mx1 = fmaxf(mx1, fmaxf(sA[n][2], sA[n][3]));
            }
            mx0 = fmaxf(mx0, __shfl_xor_sync(0xffffffffu, mx0, 1));
            mx0 = fmaxf(mx0, __shfl_xor_sync(0xffffffffu, mx0, 2));
            mx1 = fmaxf(mx1, __shfl_xor_sync(0xffffffffu, mx1, 1));
            mx1 = fmaxf(mx1, __shfl_xor_sync(0xffffffffu, mx1, 2));
            const float mn0 = fmaxf(mA0, mx0), mn1 = fmaxf(mA1, mx1);
            const float f0 = exp2p(mA0 - mn0), f1 = exp2p(mA1 - mn1);
            mA0 = mn0; mA1 = mn1;
            float sum0 = 0.f, sum1 = 0.f;
#pragma unroll
            for (int n = 0; n < 8; n++) {
                sA[n][0] = exp2p(sA[n][0] - mn0);
                sA[n][1] = exp2p(sA[n][1] - mn0);
                sA[n][2] = exp2p(sA[n][2] - mn1);
                sA[n][3] = exp2p(sA[n][3] - mn1);
                sum0 += sA[n][0] + sA[n][1];
                sum1 += sA[n][2] + sA[n][3];
            }
            lA0 = lA0 * f0 + sum0;
            lA1 = lA1 * f1 + sum1;
#pragma unroll
            for (int n = 0; n < 9; n++) {
                oA[n][0] *= f0; oA[n][1] *= f0; oA[n][2] *= f1; oA[n][3] *= f1;
            }
        }
        // ---- online softmax, subtile B ----
        {
            float mx0 = sB[0][0], mx1 = sB[0][2];
#pragma unroll
            for (int n = 0; n < 8; n++) {
                mx0 = fmaxf(mx0, fmaxf(sB[n][0], sB[n][1]));
                mx1 = fmaxf(mx1, fmaxf(sB[n][2], sB[n][3]));
            }
            mx0 = fmaxf(mx0, __shfl_xor_sync(0xffffffffu, mx0, 1));
            mx0 = fmaxf(mx0, __shfl_xor_sync(0xffffffffu, mx0, 2));
            mx1 = fmaxf(mx1, __shfl_xor_sync(0xffffffffu, mx1, 1));
            mx1 = fmaxf(mx1, __shfl_xor_sync(0xffffffffu, mx1, 2));
            const float mn0 = fmaxf(mB0, mx0), mn1 = fmaxf(mB1, mx1);
            const float f0 = exp2p(mB0 - mn0), f1 = exp2p(mB1 - mn1);
            mB0 = mn0; mB1 = mn1;
            float sum0 = 0.f, sum1 = 0.f;
#pragma unroll
            for (int n = 0; n < 8; n++) {
                sB[n][0] = exp2p(sB[n][0] - mn0);
                sB[n][1] = exp2p(sB[n][1] - mn0);
                sB[n][2] = exp2p(sB[n][2] - mn1);
                sB[n][3] = exp2p(sB[n][3] - mn1);
                sum0 += sB[n][0] + sB[n][1];
                sum1 += sB[n][2] + sB[n][3];
            }
            lB0 = lB0 * f0 + sum0;
            lB1 = lB1 * f1 + sum1;
#pragma unroll
            for (int n = 0; n < 9; n++) {
                oB[n][0] *= f0; oB[n][1] *= f0; oB[n][2] *= f1; oB[n][3] *= f1;
            }
        }

        // ---- O += P.V for both subtiles (shared V fragment loads) ----
#pragma unroll
        for (int c2 = 0; c2 < 4; c2++) {
            uint32_t phA[4], plA[4], phB[4], plB[4];
            {
                __nv_bfloat16 h00 = __float2bfloat16(sA[2*c2][0]);
                __nv_bfloat16 h01 = __float2bfloat16(sA[2*c2][1]);
                __nv_bfloat16 h02 = __float2bfloat16(sA[2*c2][2]);
                __nv_bfloat16 h03 = __float2bfloat16(sA[2*c2][3]);
                __nv_bfloat16 h10 = __float2bfloat16(sA[2*c2+1][0]);
                __nv_bfloat16 h11 = __float2bfloat16(sA[2*c2+1][1]);
                __nv_bfloat16 h12 = __float2bfloat16(sA[2*c2+1][2]);
                __nv_bfloat16 h13 = __float2bfloat16(sA[2*c2+1][3]);
                phA[0] = pk(h00, h01); phA[1] = pk(h02, h03);
                phA[2] = pk(h10, h11); phA[3] = pk(h12, h13);
                plA[0] = pk(__float2bfloat16(sA[2*c2][0]   - __bfloat162float(h00)),
                            __float2bfloat16(sA[2*c2][1]   - __bfloat162float(h01)));
                plA[1] = pk(__float2bfloat16(sA[2*c2][2]   - __bfloat162float(h02)),
                            __float2bfloat16(sA[2*c2][3]   - __bfloat162float(h03)));
                plA[2] = pk(__float2bfloat16(sA[2*c2+1][0] - __bfloat162float(h10)),
                            __float2bfloat16(sA[2*c2+1][1] - __bfloat162float(h11)));
                plA[3] = pk(__float2bfloat16(sA[2*c2+1][2] - __bfloat162float(h12)),
                            __float2bfloat16(sA[2*c2+1][3] - __bfloat162float(h13)));
            }
            {
                __nv_bfloat16 h00 = __float2bfloat16(sB[2*c2][0]);
                __nv_bfloat16 h01 = __float2bfloat16(sB[2*c2][1]);
                __nv_bfloat16 h02 = __float2bfloat16(sB[2*c2][2]);
                __nv_bfloat16 h03 = __float2bfloat16(sB[2*c2][3]);
                __nv_bfloat16 h10 = __float2bfloat16(sB[2*c2+1][0]);
                __nv_bfloat16 h11 = __float2bfloat16(sB[2*c2+1][1]);
                __nv_bfloat16 h12 = __float2bfloat16(sB[2*c2+1][2]);
                __nv_bfloat16 h13 = __float2bfloat16(sB[2*c2+1][3]);
                phB[0] = pk(h00, h01); phB[1] = pk(h02, h03);
                phB[2] = pk(h10, h11); phB[3] = pk(h12, h13);
                plB[0] = pk(__float2bfloat16(sB[2*c2][0]   - __bfloat162float(h00)),
                            __float2bfloat16(sB[2*c2][1]   - __bfloat162float(h01)));
                plB[1] = pk(__float2bfloat16(sB[2*c2][2]   - __bfloat162float(h02)),
                            __float2bfloat16(sB[2*c2][3]   - __bfloat162float(h03)));
                plB[2] = pk(__float2bfloat16(sB[2*c2+1][0] - __bfloat162float(h10)),
                            __float2bfloat16(sB[2*c2+1][1] - __bfloat162float(h11)));
                plB[3] = pk(__float2bfloat16(sB[2*c2+1][2] - __bfloat162float(h12)),
                            __float2bfloat16(sB[2*c2+1][3] - __bfloat162float(h13)));
            }

            const uint32_t vrow = sb + AVH +
                ((c2 * 16 + ((lane >> 3) & 1) * 8 + (lane & 7)) * 88) * 2;
#pragma unroll
            for (int ntp = 0; ntp < 4; ntp++) {
                uint32_t fh[4], fl[4];
                ldm4t(fh, vrow + (2 * ntp + (lane >> 4)) * 16);
                ldm4t(fl, vrow + (2 * ntp + (lane >> 4)) * 16 + 11264);
                mma16816(oA[2*ntp],     phA, &fh[0]);
                mma16816(oA[2*ntp],     plA, &fh[0]);
                mma16816(oA[2*ntp],     phA, &fl[0]);
                mma16816(oA[2*ntp + 1], phA, &fh[2]);
                mma16816(oA[2*ntp + 1], plA, &fh[2]);
                mma16816(oA[2*ntp + 1], phA, &fl[2]);
                mma16816(oB[2*ntp],     phB, &fh[0]);
                mma16816(oB[2*ntp],     plB, &fh[0]);
                mma16816(oB[2*ntp],     phB, &fl[0]);
                mma16816(oB[2*ntp + 1], phB, &fh[2]);
                mma16816(oB[2*ntp + 1], plB, &fh[2]);
                mma16816(oB[2*ntp + 1], phB, &fl[2]);
            }
            uint32_t fh2[2], fl2[2];
            ldm2t(fh2, vrow + 128);            // d cols 64..71
            ldm2t(fl2, vrow + 128 + 11264);
            mma16816(oA[8], phA, fh2);
            mma16816(oA[8], plA, fh2);
            mma16816(oA[8], phA, fl2);
            mma16816(oB[8], phB, fh2);
            mma16816(oB[8], plB, fh2);
            mma16816(oB[8], phB, fl2);
        }
        __syncthreads();
    }

    // ---- finalize ----
    lA0 += __shfl_xor_sync(0xffffffffu, lA0, 1);
    lA0 += __shfl_xor_sync(0xffffffffu, lA0, 2);
    lA1 += __shfl_xor_sync(0xffffffffu, lA1, 1);
    lA1 += __shfl_xor_sync(0xffffffffu, lA1, 2);
    lB0 += __shfl_xor_sync(0xffffffffu, lB0, 1);
    lB0 += __shfl_xor_sync(0xffffffffu, lB0, 2);
    lB1 += __shfl_xor_sync(0xffffffffu, lB1, 1);
    lB1 += __shfl_xor_sync(0xffffffffu, lB1, 2);
    const float iA0 = 1.f / lA0, iA1 = 1.f / lA1;
    const float iB0 = 1.f / lB0, iB1 = 1.f / lB1;
    const int row0 = q0 + w * 32 + g;
    const size_t baseA0 = ((size_t)((b << 10) + row0) * D_ + h * HD_);
    const size_t baseA1 = baseA0 + (size_t)8 * D_;
    const size_t baseB0 = baseA0 + (size_t)16 * D_;
    const size_t baseB1 = baseA0 + (size_t)24 * D_;
#pragma unroll
    for (int n = 0; n < 9; n++) {
        float v00 = oA[n][0] * iA0, v01 = oA[n][1] * iA0;
        float v10 = oA[n][2] * iA1, v11 = oA[n][3] * iA1;
        float w00 = oB[n][0] * iB0, w01 = oB[n][1] * iB0;
        float w10 = oB[n][2] * iB1, w11 = oB[n][3] * iB1;
        __nv_bfloat16 a00 = __float2bfloat16(v00), a01 = __float2bfloat16(v01);
        __nv_bfloat16 a10 = __float2bfloat16(v10), a11 = __float2bfloat16(v11);
        __nv_bfloat16 b00 = __float2bfloat16(w00), b01 = __float2bfloat16(w01);
        __nv_bfloat16 b10 = __float2bfloat16(w10), b11 = __float2bfloat16(w11);
        g_attnh[baseA0 + n * 8 + tg]     = a00;
        g_attnh[baseA0 + n * 8 + tg + 1] = a01;
        g_attnh[baseA1 + n * 8 + tg]     = a10;
        g_attnh[baseA1 + n * 8 + tg + 1] = a11;
        g_attnh[baseB0 + n * 8 + tg]     = b00;
        g_attnh[baseB0 + n * 8 + tg + 1] = b01;
        g_attnh[baseB1 + n * 8 + tg]     = b10;
        g_attnh[baseB1 + n * 8 + tg + 1] = b11;
        g_attnl[baseA0 + n * 8 + tg]     = __float2bfloat16(v00 - __bfloat162float(a00));
        g_attnl[baseA0 + n * 8 + tg + 1] = __float2bfloat16(v01 - __bfloat162float(a01));
        g_attnl[baseA1 + n * 8 + tg]     = __float2bfloat16(v10 - __bfloat162float(a10));
        g_attnl[baseA1 + n * 8 + tg + 1] = __float2bfloat16(v11 - __bfloat162float(a11));
        g_attnl[baseB0 + n * 8 + tg]     = __float2bfloat16(w00 - __bfloat162float(b00));
        g_attnl[baseB0 + n * 8 + tg + 1] = __float2bfloat16(w01 - __bfloat162float(b01));
        g_attnl[baseB1 + n * 8 + tg]     = __float2bfloat16(w10 - __bfloat162float(b10));
        g_attnl[baseB1 + n * 8 + tg + 1] = __float2bfloat16(w11 - __bfloat162float(b11));
    }
}

// ---------------------------------------------------------------------------
// Launch
// ---------------------------------------------------------------------------
extern "C" void kernel_launch(void* const* d_in, const int* in_sizes, int n_in,
                              void* d_out, int out_size)
{
    const float* hidden = (const float*)d_in[0];
    const float* cosp   = (const float*)d_in[1];
    const float* sinp   = (const float*)d_in[2];
    const float* qkv_w  = (const float*)d_in[3];
    const float* qkv_b  = (const float*)d_in[4];
    const float* proj_w = (const float*)d_in[5];
    const float* proj_b = (const float*)d_in[6];
    float* out = (float*)d_out;

    cudaFuncSetAttribute(gemm_bf16<1>, cudaFuncAttributeMaxDynamicSharedMemorySize, GSMEM);
    cudaFuncSetAttribute(gemm_bf16<0>, cudaFuncAttributeMaxDynamicSharedMemorySize, GSMEM);
    cudaFuncSetAttribute(attn3, cudaFuncAttributeMaxDynamicSharedMemorySize, ASM_TOT);

    // 0) pre-convert inputs/weights to hi/lo bf16
    cvt_pair<0><<<(M_ * D_ / 4 + 255) / 256, 256>>>(hidden, M_ * D_ / 4);
    cvt_pair<1><<<(N3_ * D_ / 4 + 255) / 256, 256>>>(qkv_w, N3_ * D_ / 4);
    cvt_pair<2><<<(D_ * D_ / 4 + 255) / 256, 256>>>(proj_w, D_ * D_ / 4);

    // 1) QKV GEMM -> scatter fp32 g_qkv
    {
        dim3 grid(N3_ / 128, M_ / 256);
        gemm_bf16<1><<<grid, 512, GSMEM>>>(qkv_b, nullptr, N3_);
    }
    // 2) RoPE + convert q,k,v to hi/lo bf16
    {
        const int total = 3 * B_ * H_ * S_ * 36;
        rope_cvt<<<(total + 255) / 256, 256>>>(cosp, sinp);
    }
    // 3) attention -> hi/lo bf16 g_attn
    {
        dim3 grid(B_ * H_, S_ / 256);
        attn3<<<grid, 256, ASM_TOT>>>();
    }
    // 4) output projection
    {
        dim3 grid(D_ / 128, M_ / 256);
        gemm_bf16<0><<<grid, 512, GSMEM>>>(proj_b, out, D_);
    }
}

// round 17
// speedup vs baseline: 1.4910x; 1.4910x over previous
#include <cuda_runtime.h>
#include <cuda_bf16.h>
#include <math.h>
#include <stdint.h>

#define B_   8
#define S_   1024
#define D_   1152
#define H_   16
#define HD_  72
#define M_   (B_*S_)          // 8192
#define N3_  (3*D_)           // 3456
#define BHSHD (B_*H_*S_*HD_)  // 9437184
#define SCL 0.170044411294f   // 72^-0.5 * log2(e)

// Scratch (device globals; no allocations allowed)
__device__ float g_qkv[3u*BHSHD];                         // fp32 [3][B][H][S][HD]
__device__ __nv_bfloat16 g_qkvh[3u*BHSHD], g_qkvl[3u*BHSHD];
__device__ __nv_bfloat16 g_attnh[(size_t)M_*D_], g_attnl[(size_t)M_*D_];
__device__ __nv_bfloat16 g_hidh[(size_t)M_*D_],  g_hidl[(size_t)M_*D_];
__device__ __nv_bfloat16 g_wqh[(size_t)N3_*D_],  g_wql[(size_t)N3_*D_];
__device__ __nv_bfloat16 g_wph[(size_t)D_*D_],   g_wpl[(size_t)D_*D_];

// ---------------------------------------------------------------------------
// helpers
// ---------------------------------------------------------------------------
__device__ __forceinline__ uint32_t pk(__nv_bfloat16 a, __nv_bfloat16 b) {
    return (uint32_t)__bfloat16_as_ushort(a) | ((uint32_t)__bfloat16_as_ushort(b) << 16);
}
__device__ __forceinline__ void cvt_hi_lo(float4 v, uint2& hi, uint2& lo) {
    __nv_bfloat16 hx = __float2bfloat16(v.x), hy = __float2bfloat16(v.y);
    __nv_bfloat16 hz = __float2bfloat16(v.z), hw = __float2bfloat16(v.w);
    __nv_bfloat16 lx = __float2bfloat16(v.x - __bfloat162float(hx));
    __nv_bfloat16 ly = __float2bfloat16(v.y - __bfloat162float(hy));
    __nv_bfloat16 lz = __float2bfloat16(v.z - __bfloat162float(hz));
    __nv_bfloat16 lw = __float2bfloat16(v.w - __bfloat162float(hw));
    hi.x = pk(hx, hy); hi.y = pk(hz, hw);
    lo.x = pk(lx, ly); lo.y = pk(lz, lw);
}
__device__ __forceinline__ void mma16816(float* c, const uint32_t* a, const uint32_t* b) {
    asm volatile(
        "mma.sync.aligned.m16n8k16.row.col.f32.bf16.bf16.f32 "
        "{%0,%1,%2,%3}, {%4,%5,%6,%7}, {%8,%9}, {%0,%1,%2,%3};"
        : "+f"(c[0]), "+f"(c[1]), "+f"(c[2]), "+f"(c[3])
        : "r"(a[0]), "r"(a[1]), "r"(a[2]), "r"(a[3]), "r"(b[0]), "r"(b[1]));
}
__device__ __forceinline__ void ldm4(uint32_t* r, uint32_t a) {
    asm volatile("ldmatrix.sync.aligned.m8n8.x4.shared.b16 {%0,%1,%2,%3}, [%4];"
        : "=r"(r[0]), "=r"(r[1]), "=r"(r[2]), "=r"(r[3]) : "r"(a));
}
__device__ __forceinline__ void ldm4t(uint32_t* r, uint32_t a) {
    asm volatile("ldmatrix.sync.aligned.m8n8.x4.trans.shared.b16 {%0,%1,%2,%3}, [%4];"
        : "=r"(r[0]), "=r"(r[1]), "=r"(r[2]), "=r"(r[3]) : "r"(a));
}
__device__ __forceinline__ void ldm2t(uint32_t* r, uint32_t a) {
    asm volatile("ldmatrix.sync.aligned.m8n8.x2.trans.shared.b16 {%0,%1}, [%2];"
        : "=r"(r[0]), "=r"(r[1]) : "r"(a));
}
__device__ __forceinline__ void cp16(uint32_t dst, const void* src) {
    asm volatile("cp.async.cg.shared.global [%0], [%1], 16;" :: "r"(dst), "l"(src));
}
#define CP_COMMIT() asm volatile("cp.async.commit_group;")
template <int N> __device__ __forceinline__ void cp_wait() {
    asm volatile("cp.async.wait_group %0;" :: "n"(N));
}
// FMA-pipe 2^x for x <= 0 (no MUFU)
__device__ __forceinline__ float exp2p(float d) {
    d = fmaxf(d, -100.f);
    const float MAGIC = 12582912.f;
    float frnd = d + MAGIC;
    int   i    = __float_as_int(frnd) - __float_as_int(MAGIC);
    float f    = d - (frnd - MAGIC);
    float y = 9.6181e-3f;
    y = fmaf(y, f, 5.54906e-2f);
    y = fmaf(y, f, 2.402265e-1f);
    y = fmaf(y, f, 6.931472e-1f);
    y = fmaf(y, f, 1.f);
    return __int_as_float(__float_as_int(y) + (i << 23));
}

// ---------------------------------------------------------------------------
// fp32 -> hi/lo bf16 converters
// ---------------------------------------------------------------------------
template <int WHICH>
__global__ void cvt_pair(const float* __restrict__ src, int n4)
{
    int i = blockIdx.x * blockDim.x + threadIdx.x;
    if (i >= n4) return;
    __nv_bfloat16* h = (WHICH == 0) ? g_hidh : (WHICH == 1) ? g_wqh : g_wph;
    __nv_bfloat16* l = (WHICH == 0) ? g_hidl : (WHICH == 1) ? g_wql : g_wpl;
    float4 v = ((const float4*)src)[i];
    uint2 hi, lo; cvt_hi_lo(v, hi, lo);
    ((uint2*)h)[i] = hi;
    ((uint2*)l)[i] = lo;
}

// ---------------------------------------------------------------------------
// bf16 HMMA GEMM: BM=256, BN=128, BK=32, 512 thr (16 warps), 3-stage
// cp.async ring with ONE barrier per chunk. Stage: Ah|Al|Bh|Bl (60 KB).
// The pre-compute barrier of iteration c proves all warps finished reading
// stage (c-1)%3 == (c+2)%3, so issue(c+2) may overwrite it.
// ---------------------------------------------------------------------------
#define GSTG 61440
#define GSMEM (3*GSTG)     // 184320

template <int MODE>
__global__ __launch_bounds__(512)
void gemm_bf16(const float* __restrict__ bias, float* __restrict__ C, int N)
{
    extern __shared__ __nv_bfloat16 dsm[];
    const uint32_t sb = (uint32_t)__cvta_generic_to_shared(dsm);
    const int tid = threadIdx.x, wid = tid >> 5, lane = tid & 31;
    const int bm0 = blockIdx.y * 256, bn0 = blockIdx.x * 128;
    const int wm = (wid >> 2) * 64, wn = (wid & 3) * 32;
    const int K = D_;

    const __nv_bfloat16* Ah_ = MODE ? g_hidh : g_attnh;
    const __nv_bfloat16* Al_ = MODE ? g_hidl : g_attnl;
    const __nv_bfloat16* Bh_ = MODE ? g_wqh  : g_wph;
    const __nv_bfloat16* Bl_ = MODE ? g_wql  : g_wpl;

    float acc[4][4][4];
#pragma unroll
    for (int mt = 0; mt < 4; mt++)
#pragma unroll
        for (int nt = 0; nt < 4; nt++)
#pragma unroll
            for (int r = 0; r < 4; r++) acc[mt][nt][r] = 0.f;

    const int rowL = tid >> 2;
    const int kof  = (tid & 3) * 8;

    auto issue = [&](int c, int s) {
        const uint32_t stb = sb + s * GSTG;
        const int k0 = c * 32;
        cp16(stb +         rowL * 80 + kof * 2,         Ah_ + (size_t)(bm0 + rowL) * K + k0 + kof);
        cp16(stb +         (rowL + 128) * 80 + kof * 2, Ah_ + (size_t)(bm0 + rowL + 128) * K + k0 + kof);
        cp16(stb + 20480 + rowL * 80 + kof * 2,         Al_ + (size_t)(bm0 + rowL) * K + k0 + kof);
        cp16(stb + 20480 + (rowL + 128) * 80 + kof * 2, Al_ + (size_t)(bm0 + rowL + 128) * K + k0 + kof);
        cp16(stb + 40960 + rowL * 80 + kof * 2,         Bh_ + (size_t)(bn0 + rowL) * K + k0 + kof);
        cp16(stb + 51200 + rowL * 80 + kof * 2,         Bl_ + (size_t)(bn0 + rowL) * K + k0 + kof);
        CP_COMMIT();
    };

    const int NCH = K / 32;   // 36
    issue(0, 0);
    issue(1, 1);
    for (int c = 0; c < NCH; c++) {
        if (c + 2 < NCH) cp_wait<1>(); else cp_wait<0>();
        __syncthreads();
        if (c + 2 < NCH) issue(c + 2, (c + 2) % 3);
        const uint32_t stb = sb + (c % 3) * GSTG;
        const uint32_t abase = stb + ((wm + (lane & 15)) * 40 + ((lane >> 4) * 8)) * 2;
        const uint32_t bbase = stb + 40960 +
            ((wn + ((lane >> 4) * 8) + (lane & 7)) * 40 + (((lane >> 3) & 1) * 8)) * 2;
#pragma unroll
        for (int ks = 0; ks < 2; ks++) {
            uint32_t bhf[8], blf[8];
            ldm4(&bhf[0], bbase + ks * 32);
            ldm4(&bhf[4], bbase + ks * 32 + 1280);
            ldm4(&blf[0], bbase + ks * 32 + 10240);
            ldm4(&blf[4], bbase + ks * 32 + 10240 + 1280);
#pragma unroll
            for (int mt = 0; mt < 4; mt++) {
                uint32_t ah[4], al[4];
                ldm4(ah, abase + ks * 32 + mt * 1280);
                ldm4(al, abase + ks * 32 + mt * 1280 + 20480);
#pragma unroll
                for (int nt = 0; nt < 4; nt++) {
                    mma16816(acc[mt][nt], ah, &bhf[nt * 2]);
                    mma16816(acc[mt][nt], ah, &blf[nt * 2]);
                    mma16816(acc[mt][nt], al, &bhf[nt * 2]);
                }
            }
        }
    }

    const int g = lane >> 2, tg = (lane & 3) * 2;
#pragma unroll
    for (int mt = 0; mt < 4; mt++) {
#pragma unroll
        for (int nt = 0; nt < 4; nt++) {
#pragma unroll
            for (int r = 0; r < 4; r++) {
                const int m = bm0 + wm + mt * 16 + g + (r >= 2 ? 8 : 0);
                const int n = bn0 + wn + nt * 8 + tg + (r & 1);
                const float v = acc[mt][nt][r] + bias[n];
                if (MODE == 0) {
                    C[(size_t)m * N + n] = v;
                } else {
                    const int b = m >> 10, s2 = m & 1023;
                    const int t = n / D_;
                    const int rr = n - t * D_;
                    const int h = rr / HD_;
                    const int hd = rr - h * HD_;
                    g_qkv[(((size_t)(t * B_ + b) * H_ + h) * S_ + s2) * HD_ + hd] = v;
                }
            }
        }
    }
}

// ---------------------------------------------------------------------------
// RoPE + convert (unchanged)
// ---------------------------------------------------------------------------
__global__ void rope_cvt(const float* __restrict__ cosp,
                         const float* __restrict__ sinp)
{
    const int total = 3 * B_ * H_ * S_ * 36;
    int idx = blockIdx.x * blockDim.x + threadIdx.x;
    if (idx >= total) return;
    const int i = idx % 36;
    const int row = idx / 36;
    const int s = row & (S_ - 1);
    const int t = row >> 17;
    const float* base = g_qkv + (size_t)row * HD_;
    float x1 = base[i], x2 = base[i + 36];
    float y1, y2;
    if (t < 2) {
        y1 = x1 * cosp[s * HD_ + i]      - x2 * sinp[s * HD_ + i];
        y2 = x2 * cosp[s * HD_ + i + 36] + x1 * sinp[s * HD_ + i + 36];
        if (t == 0) { y1 *= SCL; y2 *= SCL; }
    } else { y1 = x1; y2 = x2; }
    __nv_bfloat16 h1 = __float2bfloat16(y1);
    __nv_bfloat16 h2 = __float2bfloat16(y2);
    const size_t o1 = (size_t)row * HD_ + i, o2 = o1 + 36;
    g_qkvh[o1] = h1; g_qkvl[o1] = __float2bfloat16(y1 - __bfloat162float(h1));
    g_qkvh[o2] = h2; g_qkvl[o2] = __float2bfloat16(y2 - __bfloat162float(h2));
}

// ---------------------------------------------------------------------------
// HMMA flash attention v4 (kept from R13; deflated data says it wins):
// 32 q-rows per warp, shared K/V fragment loads, Q persistent in smem.
// ---------------------------------------------------------------------------
#define AQL 45056
#define AKH 90112
#define AKL 101376
#define AVH 112640
#define AVL 123904
#define ASM_TOT 135168

__global__ __launch_bounds__(256)
void attn3()
{
    extern __shared__ __nv_bfloat16 sm[];
    const uint32_t sb = (uint32_t)__cvta_generic_to_shared(sm);
    const int tid = threadIdx.x, w = tid >> 5, lane = tid & 31;
    const int g = lane >> 2, tg = (lane & 3) * 2;
    const int bh = blockIdx.x, q0 = blockIdx.y * 256;
    const int b = bh >> 4, h = bh & 15;

    const __nv_bfloat16* qh = g_qkvh;
    const __nv_bfloat16* ql = g_qkvl;
    const __nv_bfloat16* kh = g_qkvh + (size_t)BHSHD;
    const __nv_bfloat16* kl = g_qkvl + (size_t)BHSHD;
    const __nv_bfloat16* vh = g_qkvh + (size_t)2 * BHSHD;
    const __nv_bfloat16* vl = g_qkvl + (size_t)2 * BHSHD;

    // ---- stage Q (persistent; already SCL-scaled) ----
    for (int i = tid; i < 256 * 18; i += 256) {
        const int row = i / 18, c4 = (i % 18) * 4;
        const size_t go = ((size_t)(bh << 10) + q0 + row) * HD_ + c4;
        *(uint2*)&sm[row * 88 + c4]         = *(const uint2*)&qh[go];
        *(uint2*)&sm[22528 + row * 88 + c4] = *(const uint2*)&ql[go];
    }
    for (int i = tid; i < 2048; i += 256) {     // zero Q pad cols 72..79 (hi+lo)
        const int arr = i >> 10, rem = i & 1023;
        const int row = rem >> 2, c = (rem & 3) * 2;
        *(uint32_t*)&sm[arr * 22528 + row * 88 + 72 + c] = 0u;
    }
    // ---- zero K pad cols 72..79 (hi+lo) ----
    for (int i = tid; i < 512; i += 256) {
        const int arr = i >> 8, rem = i & 255;
        const int row = rem >> 2, c = (rem & 3) * 2;
        *(uint32_t*)&sm[45056 + arr * 5632 + row * 88 + 72 + c] = 0u;
    }
    __syncthreads();

    float oA[9][4], oB[9][4];
#pragma unroll
    for (int n = 0; n < 9; n++)
#pragma unroll
        for (int r = 0; r < 4; r++) { oA[n][r] = 0.f; oB[n][r] = 0.f; }
    float mA0 = -1e30f, mA1 = -1e30f, lA0 = 0.f, lA1 = 0.f;
    float mB0 = -1e30f, mB1 = -1e30f, lB0 = 0.f, lB1 = 0.f;

    const uint32_t qbA = sb + ((w * 32 + (lane & 15)) * 88 + ((lane >> 4) * 8)) * 2;
    const uint32_t qbB = qbA + 2816;   // +16 rows
    const uint32_t kb0 = sb + AKH +
        ((((lane >> 4) * 8) + (lane & 7)) * 88 + (((lane >> 3) & 1) * 8)) * 2;

    for (int j0 = 0; j0 < S_; j0 += 64) {
        // ---- stage K and V (straight row copies, bf16) ----
        for (int i = tid; i < 64 * 18; i += 256) {
            const int row = i / 18, c4 = (i % 18) * 4;
            const size_t go = ((size_t)(bh << 10) + j0 + row) * HD_ + c4;
            *(uint2*)&sm[45056 + row * 88 + c4] = *(const uint2*)&kh[go];
            *(uint2*)&sm[50688 + row * 88 + c4] = *(const uint2*)&kl[go];
            *(uint2*)&sm[56320 + row * 88 + c4] = *(const uint2*)&vh[go];
            *(uint2*)&sm[61952 + row * 88 + c4] = *(const uint2*)&vl[go];
        }
        __syncthreads();

        // ---- S = Q.K^T for both subtiles ----
        float sA[8][4], sB[8][4];
#pragma unroll
        for (int n = 0; n < 8; n++)
#pragma unroll
            for (int r = 0; r < 4; r++) { sA[n][r] = 0.f; sB[n][r] = 0.f; }
#pragma unroll
        for (int c = 0; c < 5; c++) {
            uint32_t qah[4], qal[4], qbh[4], qbl[4];
            ldm4(qah, qbA + c * 32);
            ldm4(qal, qbA + c * 32 + AQL);
            ldm4(qbh, qbB + c * 32);
            ldm4(qbl, qbB + c * 32 + AQL);
#pragma unroll
            for (int ktp = 0; ktp < 4; ktp++) {
                uint32_t fh[4], fl[4];
                ldm4(fh, kb0 + c * 32 + ktp * 2816);
                ldm4(fl, kb0 + c * 32 + ktp * 2816 + 11264);
                mma16816(sA[ktp * 2],     qah, &fh[0]);
                mma16816(sA[ktp * 2],     qah, &fl[0]);
                mma16816(sA[ktp * 2],     qal, &fh[0]);
                mma16816(sA[ktp * 2 + 1], qah, &fh[2]);
                mma16816(sA[ktp * 2 + 1], qah, &fl[2]);
                mma16816(sA[ktp * 2 + 1], qal, &fh[2]);
                mma16816(sB[ktp * 2],     qbh, &fh[0]);
                mma16816(sB[ktp * 2],     qbh, &fl[0]);
                mma16816(sB[ktp * 2],     qbl, &fh[0]);
                mma16816(sB[ktp * 2 + 1], qbh, &fh[2]);
                mma16816(sB[ktp * 2 + 1], qbh, &fl[2]);
                mma16816(sB[ktp * 2 + 1], qbl, &fh[2]);
            }
        }

        // ---- online softmax, subtile A ----
        {
            float mx0 = sA[0][0], mx1 = sA[0][2];
#pragma unroll
            for (int n = 0; n < 8; n++) {
                mx0 = fmaxf(mx0, fmaxf(sA[n][0], sA[n][1]));
                mx1 = fmaxf(mx1, fmaxf(sA[n][2], sA[n][3]));
            }
            mx0 = fmaxf(mx0, __shfl_xor_sync(0xffffffffu, mx0, 1));
            mx0 = fmaxf(mx0, __shfl_xor_sync(0xffffffffu, mx0, 2));
            mx1 = fmaxf(mx1, __shfl_xor_sync(0xffffffffu, mx1, 1));
            mx1 = fmaxf(mx1, __shfl_xor_sync(0xffffffffu, mx1, 2));
            const float mn0 = fmaxf(mA0, mx0), mn1 = fmaxf(mA1, mx1);
            const float f0 = exp2p(mA0 - mn0), f1 = exp2p(mA1 - mn1);
            mA0 = mn0; mA1 = mn1;
            float sum0 = 0.f, sum1 = 0.f;
#pragma unroll
            for (int n = 0; n < 8; n++) {
                sA[n][0] = exp2p(sA[n][0] - mn0);
                sA[n][1] = exp2p(sA[n][1] - mn0);
                sA[n][2] = exp2p(sA[n][2] - mn1);
                sA[n][3] = exp2p(sA[n][3] - mn1);
                sum0 += sA[n][0] + sA[n][1];
                sum1 += sA[n][2] + sA[n][3];
            }
            lA0 = lA0 * f0 + sum0;
            lA1 = lA1 * f1 + sum1;
#pragma unroll
            for (int n = 0; n < 9; n++) {
                oA[n][0] *= f0; oA[n][1] *= f0; oA[n][2] *= f1; oA[n][3] *= f1;
            }
        }
        // ---- online softmax, subtile B ----
        {
            float mx0 = sB[0][0], mx1 = sB[0][2];
#pragma unroll
            for (int n = 0; n < 8; n++) {
                mx0 = fmaxf(mx0, fmaxf(sB[n][0], sB[n][1]));
                mx1 = fmaxf(mx1, fmaxf(sB[n][2], sB[n][3]));
            }
            mx0 = fmaxf(mx0, __shfl_xor_sync(0xffffffffu, mx0, 1));
            mx0 = fmaxf(mx0, __shfl_xor_sync(0xffffffffu, mx0, 2));
            mx1 = fmaxf(mx1, __shfl_xor_sync(0xffffffffu, mx1, 1));
            mx1 = fmaxf(mx1, __shfl_xor_sync(0xffffffffu, mx1, 2));
            const float mn0 = fmaxf(mB0, mx0), mn1 = fmaxf(mB1, mx1);
            const float f0 = exp2p(mB0 - mn0), f1 = exp2p(mB1 - mn1);
            mB0 = mn0; mB1 = mn1;
            float sum0 = 0.f, sum1 = 0.f;
#pragma unroll
            for (int n = 0; n < 8; n++) {
                sB[n][0] = exp2p(sB[n][0] - mn0);
                sB[n][1] = exp2p(sB[n][1] - mn0);
                sB[n][2] = exp2p(sB[n][2] - mn1);
                sB[n][3] = exp2p(sB[n][3] - mn1);
                sum0 += sB[n][0] + sB[n][1];
                sum1 += sB[n][2] + sB[n][3];
            }
            lB0 = lB0 * f0 + sum0;
            lB1 = lB1 * f1 + sum1;
#pragma unroll
            for (int n = 0; n < 9; n++) {
                oB[n][0] *= f0; oB[n][1] *= f0; oB[n][2] *= f1; oB[n][3] *= f1;
            }
        }

        // ---- O += P.V for both subtiles (shared V fragment loads) ----
#pragma unroll
        for (int c2 = 0; c2 < 4; c2++) {
            uint32_t phA[4], plA[4], phB[4], plB[4];
            {
                __nv_bfloat16 h00 = __float2bfloat16(sA[2*c2][0]);
                __nv_bfloat16 h01 = __float2bfloat16(sA[2*c2][1]);
                __nv_bfloat16 h02 = __float2bfloat16(sA[2*c2][2]);
                __nv_bfloat16 h03 = __float2bfloat16(sA[2*c2][3]);
                __nv_bfloat16 h10 = __float2bfloat16(sA[2*c2+1][0]);
                __nv_bfloat16 h11 = __float2bfloat16(sA[2*c2+1][1]);
                __nv_bfloat16 h12 = __float2bfloat16(sA[2*c2+1][2]);
                __nv_bfloat16 h13 = __float2bfloat16(sA[2*c2+1][3]);
                phA[0] = pk(h00, h01); phA[1] = pk(h02, h03);
                phA[2] = pk(h10, h11); phA[3] = pk(h12, h13);
                plA[0] = pk(__float2bfloat16(sA[2*c2][0]   - __bfloat162float(h00)),
                            __float2bfloat16(sA[2*c2][1]   - __bfloat162float(h01)));
                plA[1] = pk(__float2bfloat16(sA[2*c2][2]   - __bfloat162float(h02)),
                            __float2bfloat16(sA[2*c2][3]   - __bfloat162float(h03)));
                plA[2] = pk(__float2bfloat16(sA[2*c2+1][0] - __bfloat162float(h10)),
                            __float2bfloat16(sA[2*c2+1][1] - __bfloat162float(h11)));
                plA[3] = pk(__float2bfloat16(sA[2*c2+1][2] - __bfloat162float(h12)),
                            __float2bfloat16(sA[2*c2+1][3] - __bfloat162float(h13)));
            }
            {
                __nv_bfloat16 h00 = __float2bfloat16(sB[2*c2][0]);
                __nv_bfloat16 h01 = __float2bfloat16(sB[2*c2][1]);
                __nv_bfloat16 h02 = __float2bfloat16(sB[2*c2][2]);
                __nv_bfloat16 h03 = __float2bfloat16(sB[2*c2][3]);
                __nv_bfloat16 h10 = __float2bfloat16(sB[2*c2+1][0]);
                __nv_bfloat16 h11 = __float2bfloat16(sB[2*c2+1][1]);
                __nv_bfloat16 h12 = __float2bfloat16(sB[2*c2+1][2]);
                __nv_bfloat16 h13 = __float2bfloat16(sB[2*c2+1][3]);
                phB[0] = pk(h00, h01); phB[1] = pk(h02, h03);
                phB[2] = pk(h10, h11); phB[3] = pk(h12, h13);
                plB[0] = pk(__float2bfloat16(sB[2*c2][0]   - __bfloat162float(h00)),
                            __float2bfloat16(sB[2*c2][1]   - __bfloat162float(h01)));
                plB[1] = pk(__float2bfloat16(sB[2*c2][2]   - __bfloat162float(h02)),
                            __float2bfloat16(sB[2*c2][3]   - __bfloat162float(h03)));
                plB[2] = pk(__float2bfloat16(sB[2*c2+1][0] - __bfloat162float(h10)),
                            __float2bfloat16(sB[2*c2+1][1] - __bfloat162float(h11)));
                plB[3] = pk(__float2bfloat16(sB[2*c2+1][2] - __bfloat162float(h12)),
                            __float2bfloat16(sB[2*c2+1][3] - __bfloat162float(h13)));
            }

            const uint32_t vrow = sb + AVH +
                ((c2 * 16 + ((lane >> 3) & 1) * 8 + (lane & 7)) * 88) * 2;
#pragma unroll
            for (int ntp = 0; ntp < 4; ntp++) {
                uint32_t fh[4], fl[4];
                ldm4t(fh, vrow + (2 * ntp + (lane >> 4)) * 16);
                ldm4t(fl, vrow + (2 * ntp + (lane >> 4)) * 16 + 11264);
                mma16816(oA[2*ntp],     phA, &fh[0]);
                mma16816(oA[2*ntp],     plA, &fh[0]);
                mma16816(oA[2*ntp],     phA, &fl[0]);
                mma16816(oA[2*ntp + 1], phA, &fh[2]);
                mma16816(oA[2*ntp + 1], plA, &fh[2]);
                mma16816(oA[2*ntp + 1], phA, &fl[2]);
                mma16816(oB[2*ntp],     phB, &fh[0]);
                mma16816(oB[2*ntp],     plB, &fh[0]);
                mma16816(oB[2*ntp],     phB, &fl[0]);
                mma16816(oB[2*ntp + 1], phB, &fh[2]);
                mma16816(oB[2*ntp + 1], plB, &fh[2]);
                mma16816(oB[2*ntp + 1], phB, &fl[2]);
            }
            uint32_t fh2[2], fl2[2];
            ldm2t(fh2, vrow + 128);            // d cols 64..71
            ldm2t(fl2, vrow + 128 + 11264);
            mma16816(oA[8], phA, fh2);
            mma16816(oA[8], plA, fh2);
            mma16816(oA[8], phA, fl2);
            mma16816(oB[8], phB, fh2);
            mma16816(oB[8], plB, fh2);
            mma16816(oB[8], phB, fl2);
        }
        __syncthreads();
    }

    // ---- finalize ----
    lA0 += __shfl_xor_sync(0xffffffffu, lA0, 1);
    lA0 += __shfl_xor_sync(0xffffffffu, lA0, 2);
    lA1 += __shfl_xor_sync(0xffffffffu, lA1, 1);
    lA1 += __shfl_xor_sync(0xffffffffu, lA1, 2);
    lB0 += __shfl_xor_sync(0xffffffffu, lB0, 1);
    lB0 += __shfl_xor_sync(0xffffffffu, lB0, 2);
    lB1 += __shfl_xor_sync(0xffffffffu, lB1, 1);
    lB1 += __shfl_xor_sync(0xffffffffu, lB1, 2);
    const float iA0 = 1.f / lA0, iA1 = 1.f / lA1;
    const float iB0 = 1.f / lB0, iB1 = 1.f / lB1;
    const int row0 = q0 + w * 32 + g;
    const size_t baseA0 = ((size_t)((b << 10) + row0) * D_ + h * HD_);
    const size_t baseA1 = baseA0 + (size_t)8 * D_;
    const size_t baseB0 = baseA0 + (size_t)16 * D_;
    const size_t baseB1 = baseA0 + (size_t)24 * D_;
#pragma unroll
    for (int n = 0; n < 9; n++) {
        float v00 = oA[n][0] * iA0, v01 = oA[n][1] * iA0;
        float v10 = oA[n][2] * iA1, v11 = oA[n][3] * iA1;
        float w00 = oB[n][0] * iB0, w01 = oB[n][1] * iB0;
        float w10 = oB[n][2] * iB1, w11 = oB[n][3] * iB1;
        __nv_bfloat16 a00 = __float2bfloat16(v00), a01 = __float2bfloat16(v01);
        __nv_bfloat16 a10 = __float2bfloat16(v10), a11 = __float2bfloat16(v11);
        __nv_bfloat16 b00 = __float2bfloat16(w00), b01 = __float2bfloat16(w01);
        __nv_bfloat16 b10 = __float2bfloat16(w10), b11 = __float2bfloat16(w11);
        g_attnh[baseA0 + n * 8 + tg]     = a00;
        g_attnh[baseA0 + n * 8 + tg + 1] = a01;
        g_attnh[baseA1 + n * 8 + tg]     = a10;
        g_attnh[baseA1 + n * 8 + tg + 1] = a11;
        g_attnh[baseB0 + n * 8 + tg]     = b00;
        g_attnh[baseB0 + n * 8 + tg + 1] = b01;
        g_attnh[baseB1 + n * 8 + tg]     = b10;
        g_attnh[baseB1 + n * 8 + tg + 1] = b11;
        g_attnl[baseA0 + n * 8 + tg]     = __float2bfloat16(v00 - __bfloat162float(a00));
        g_attnl[baseA0 + n * 8 + tg + 1] = __float2bfloat16(v01 - __bfloat162float(a01));
        g_attnl[baseA1 + n * 8 + tg]     = __float2bfloat16(v10 - __bfloat162float(a10));
        g_attnl[baseA1 + n * 8 + tg + 1] = __float2bfloat16(v11 - __bfloat162float(a11));
        g_attnl[baseB0 + n * 8 + tg]     = __float2bfloat16(w00 - __bfloat162float(b00));
        g_attnl[baseB0 + n * 8 + tg + 1] = __float2bfloat16(w01 - __bfloat162float(b01));
        g_attnl[baseB1 + n * 8 + tg]     = __float2bfloat16(w10 - __bfloat162float(b10));
        g_attnl[baseB1 + n * 8 + tg + 1] = __float2bfloat16(w11 - __bfloat162float(b11));
    }
}

// ---------------------------------------------------------------------------
// Launch
// ---------------------------------------------------------------------------
extern "C" void kernel_launch(void* const* d_in, const int* in_sizes, int n_in,
                              void* d_out, int out_size)
{
    const float* hidden = (const float*)d_in[0];
    const float* cosp   = (const float*)d_in[1];
    const float* sinp   = (const float*)d_in[2];
    const float* qkv_w  = (const float*)d_in[3];
    const float* qkv_b  = (const float*)d_in[4];
    const float* proj_w = (const float*)d_in[5];
    const float* proj_b = (const float*)d_in[6];
    float* out = (float*)d_out;

    cudaFuncSetAttribute(gemm_bf16<1>, cudaFuncAttributeMaxDynamicSharedMemorySize, GSMEM);
    cudaFuncSetAttribute(gemm_bf16<0>, cudaFuncAttributeMaxDynamicSharedMemorySize, GSMEM);
    cudaFuncSetAttribute(attn3, cudaFuncAttributeMaxDynamicSharedMemorySize, ASM_TOT);

    // 0) pre-convert inputs/weights to hi/lo bf16
    cvt_pair<0><<<(M_ * D_ / 4 + 255) / 256, 256>>>(hidden, M_ * D_ / 4);
    cvt_pair<1><<<(N3_ * D_ / 4 + 255) / 256, 256>>>(qkv_w, N3_ * D_ / 4);
    cvt_pair<2><<<(D_ * D_ / 4 + 255) / 256, 256>>>(proj_w, D_ * D_ / 4);

    // 1) QKV GEMM -> scatter fp32 g_qkv
    {
        dim3 grid(N3_ / 128, M_ / 256);
        gemm_bf16<1><<<grid, 512, GSMEM>>>(qkv_b, nullptr, N3_);
    }
    // 2) RoPE + convert q,k,v to hi/lo bf16
    {
        const int total = 3 * B_ * H_ * S_ * 36;
        rope_cvt<<<(total + 255) / 256, 256>>>(cosp, sinp);
    }
    // 3) attention -> hi/lo bf16 g_attn
    {
        dim3 grid(B_ * H_, S_ / 256);
        attn3<<<grid, 256, ASM_TOT>>>();
    }
    // 4) output projection
    {
        dim3 grid(D_ / 128, M_ / 256);
        gemm_bf16<0><<<grid, 512, GSMEM>>>(proj_b, out, D_);
    }
}